// round 7
// baseline (speedup 1.0000x reference)
#include <cuda_runtime.h>
#include <stdint.h>

#define BB 4
#define SS 2048
#define DD 1024
#define EE 64
#define CC 64
#define ROWS (BB*SS)          // 8192
#define NOISE_SCALE (1.0f/64.0f)
#define HALF ((size_t)BB*SS*EE*CC)      // elements per output array

// Scratch: gates transposed [b][e][s]  (2 MB)
__device__ float g_gatesT[(size_t)BB*EE*SS];

__device__ __forceinline__ float2 ffma2(float2 a, float2 b, float2 c) {
    unsigned long long au = *reinterpret_cast<unsigned long long*>(&a);
    unsigned long long bu = *reinterpret_cast<unsigned long long*>(&b);
    unsigned long long cu = *reinterpret_cast<unsigned long long*>(&c);
    unsigned long long du;
    asm("fma.rn.f32x2 %0, %1, %2, %3;" : "=l"(du) : "l"(au), "l"(bu), "l"(cu));
    return *reinterpret_cast<float2*>(&du);
}

// ---------------------------------------------------------------------------
// Kernel 1: f32x2 GEMM + noise + softmax -> gatesT.
// 128 blocks x 128 threads; tile 64 rows x 64 experts; per-thread 4 rows x
// 8 experts (16 FFMA2 per kk against 2 LDS.128 + 4 LDS.64 = 1.0 smem B/MAC,
// FFMA2-pipe-bound, not crossbar-bound).
// ---------------------------------------------------------------------------
__global__ __launch_bounds__(128, 1)
void gemm_softmax_kernel(const float* __restrict__ X,
                         const float* __restrict__ W,
                         const float* __restrict__ noise)
{
    __shared__ float2 As2[64][65];   // [row][k] splat; pad 65 -> conflict-free
    __shared__ float  Ws[64][64];    // [k][expert]; reused for logits

    const int tid  = threadIdx.x;
    const int tx   = tid & 7;        // expert octet: experts tx*8..tx*8+7
    const int ty   = tid >> 3;       // row quad: rows ty*4..ty*4+3
    const int row0 = blockIdx.x * 64;

    float2 acc[4][4];
#pragma unroll
    for (int i = 0; i < 4; i++)
#pragma unroll
        for (int j = 0; j < 4; j++) acc[i][j] = make_float2(0.f, 0.f);

    for (int k0 = 0; k0 < DD; k0 += 64) {
        // A tile: 64 rows x 64 k (1024 float4, 8 per thread), splat to float2
#pragma unroll
        for (int p = 0; p < 8; p++) {
            int r  = (tid >> 4) + p * 8;
            int kv = (tid & 15) * 4;
            float4 v = *(const float4*)&X[(size_t)(row0 + r) * DD + k0 + kv];
            As2[r][kv + 0] = make_float2(v.x, v.x);
            As2[r][kv + 1] = make_float2(v.y, v.y);
            As2[r][kv + 2] = make_float2(v.z, v.z);
            As2[r][kv + 3] = make_float2(v.w, v.w);
        }
        // W tile: 64 k x 64 experts (1024 float4, 8 per thread)
#pragma unroll
        for (int p = 0; p < 8; p++) {
            int kk = (tid >> 4) + p * 8;
            int ev = (tid & 15) * 4;
            *(float4*)&Ws[kk][ev] = *(const float4*)&W[(size_t)(k0 + kk) * EE + ev];
        }
        __syncthreads();

#pragma unroll 16
        for (int kk = 0; kk < 64; kk++) {
            float4 b0 = *(const float4*)&Ws[kk][tx * 8];
            float4 b1 = *(const float4*)&Ws[kk][tx * 8 + 4];
            float2 p0 = make_float2(b0.x, b0.y);
            float2 p1 = make_float2(b0.z, b0.w);
            float2 p2 = make_float2(b1.x, b1.y);
            float2 p3 = make_float2(b1.z, b1.w);
#pragma unroll
            for (int i = 0; i < 4; i++) {
                float2 a = As2[ty * 4 + i][kk];
                acc[i][0] = ffma2(a, p0, acc[i][0]);
                acc[i][1] = ffma2(a, p1, acc[i][1]);
                acc[i][2] = ffma2(a, p2, acc[i][2]);
                acc[i][3] = ffma2(a, p3, acc[i][3]);
            }
        }
        __syncthreads();
    }

    // Epilogue: logits + noise into Ws (reused as [row][expert])
#pragma unroll
    for (int i = 0; i < 4; i++) {
        int r   = ty * 4 + i;
        int row = row0 + r;
#pragma unroll
        for (int j = 0; j < 4; j++) {
            int e0 = tx * 8 + j * 2;
            float2 v = acc[i][j];
            Ws[r][e0 + 0] = v.x + noise[(size_t)row * EE + e0 + 0] * NOISE_SCALE;
            Ws[r][e0 + 1] = v.y + noise[(size_t)row * EE + e0 + 1] * NOISE_SCALE;
        }
    }
    __syncthreads();

    // Softmax per row (threads 0..63), write transposed gates.
    if (tid < 64) {
        int r   = tid;
        int row = row0 + r;
        int b   = row / SS;
        int s   = row % SS;
        float m = -1e30f;
#pragma unroll
        for (int e = 0; e < EE; e++) m = fmaxf(m, Ws[r][e]);
        float sum = 0.0f;
#pragma unroll
        for (int e = 0; e < EE; e++) {
            float t = expf(Ws[r][e] - m);
            Ws[r][e] = t;
            sum += t;
        }
        float inv = 1.0f / sum;
#pragma unroll
        for (int e = 0; e < EE; e++) {
            g_gatesT[((size_t)b * EE + e) * SS + s] = Ws[r][e] * inv;
        }
    }
}

// ---------------------------------------------------------------------------
// Kernel 2: per-(b,e) exact top-64 via MSD radix select on u64 keys
// (gate_bits<<32)|~idx (distinct), parallel suffix-scan digit selection,
// adaptive bitonic sort of candidates, scatter. Grid: 256 blocks, 512 thr.
// ---------------------------------------------------------------------------
__global__ __launch_bounds__(512, 2)
void topk_kernel(float* __restrict__ mask_out,
                 float* __restrict__ comb_out)
{
    __shared__ unsigned long long keys[SS];
    __shared__ unsigned long long cand[512];
    __shared__ int hist[256];
    __shared__ unsigned long long s_prefix, s_thresh;
    __shared__ int s_need, s_done, s_cnt;

    const int tid = threadIdx.x;
    const int b = blockIdx.x >> 6;
    const int e = blockIdx.x & 63;

    const float* col = &g_gatesT[((size_t)b * EE + e) * SS];
    for (int i = tid; i < SS; i += 512) {
        unsigned int fb = __float_as_uint(col[i]);   // softmax gates > 0
        keys[i] = ((unsigned long long)fb << 32) | (unsigned int)(~i);
    }
    if (tid == 0) { s_done = 0; s_need = CC; s_prefix = 0ULL; }
    __syncthreads();

    // MSD radix select, 8-bit digits. Exits when candidate set <= 512.
    for (int shift = 56; shift >= 0; shift -= 8) {
        if (s_done) break;
        const unsigned long long pf = s_prefix;
        const int need = s_need;
        if (tid < 256) hist[tid] = 0;
        __syncthreads();
        for (int i = tid; i < SS; i += 512) {
            unsigned long long k = keys[i];
            bool active = (shift == 56) || ((k >> (shift + 8)) == pf);
            if (active) atomicAdd(&hist[(int)((k >> shift) & 255)], 1);
        }
        __syncthreads();

        // Parallel suffix sum over 256 bins (Hillis-Steele, 8 rounds).
#pragma unroll
        for (int off = 1; off < 256; off <<= 1) {
            int v = 0;
            if (tid < 256) {
                v = hist[tid];
                if (tid + off < 256) v += hist[tid + off];
            }
            __syncthreads();
            if (tid < 256) hist[tid] = v;
            __syncthreads();
        }

        // Exactly one bin d satisfies sfx[d] >= need > sfx[d+1].
        if (tid < 256) {
            int c     = hist[tid];
            int above = (tid == 255) ? 0 : hist[tid + 1];
            if (c >= need && above < need) {
                int got = (CC - need) + c;
                unsigned long long np = (pf << 8) | (unsigned long long)tid;
                if (got <= 512 || shift == 0) {
                    s_thresh = np << shift;
                    s_done = 1;
                } else {
                    s_need = need - above;
                    s_prefix = np;
                }
            }
        }
        __syncthreads();
    }

    // Collect candidates (>= threshold); pad with 0 (all real keys > 0).
    cand[tid & 511] = 0ULL;
    if (tid == 0) s_cnt = 0;
    __syncthreads();
    {
        const unsigned long long T = s_thresh;
        for (int i = tid; i < SS; i += 512) {
            unsigned long long k = keys[i];
            if (k >= T) { int p = atomicAdd(&s_cnt, 1); if (p < 512) cand[p] = k; }
        }
    }
    __syncthreads();

    // Adaptive bitonic sort (descending): nsort = next pow2 >= max(cnt, 64).
    int cnt = s_cnt;
    int nsort = 64;
    while (nsort < cnt && nsort < 512) nsort <<= 1;

    for (int k2 = 2; k2 <= nsort; k2 <<= 1) {
        for (int j = k2 >> 1; j > 0; j >>= 1) {
            if (tid < (nsort >> 1)) {
                int i   = ((tid & ~(j - 1)) << 1) | (tid & (j - 1));
                int ixj = i | j;
                bool desc = ((i & k2) == 0);
                unsigned long long a = cand[i];
                unsigned long long c = cand[ixj];
                if ((a < c) == desc) { cand[i] = c; cand[ixj] = a; }
            }
            __syncthreads();
        }
    }

    // Scatter top-64 (rank = c)
    if (tid < CC) {
        unsigned long long k = cand[tid];
        int   s = (int)(~(unsigned int)k);
        float v = __uint_as_float((unsigned int)(k >> 32));
        size_t idx = ((((size_t)b * SS + s) * EE + e) << 6) + tid;
        mask_out[idx] = 1.0f;
        comb_out[idx] = v;
    }
}

// ---------------------------------------------------------------------------
// Launch: driver memset (fastest observed 268MB zero) forked onto a side
// stream; gemm on main stream; join; then select+scatter. Worst case the
// branches serialize (R3 evidence) -> still the optimized serial sum.
// ---------------------------------------------------------------------------
static cudaStream_t g_s2;
static cudaEvent_t  g_evFork, g_evJoin;
static bool         g_init = false;

extern "C" void kernel_launch(void* const* d_in, const int* in_sizes, int n_in,
                              void* d_out, int out_size)
{
    const float* X     = (const float*)d_in[0];   // [B,S,D]
    const float* W     = (const float*)d_in[1];   // [D,E]
    const float* noise = (const float*)d_in[2];   // [B,S,E]
    float* out = (float*)d_out;

    if (!g_init) {
        cudaStreamCreateWithFlags(&g_s2, cudaStreamNonBlocking);
        cudaEventCreateWithFlags(&g_evFork, cudaEventDisableTiming);
        cudaEventCreateWithFlags(&g_evJoin, cudaEventDisableTiming);
        g_init = true;
    }

    cudaEventRecord(g_evFork, 0);
    cudaStreamWaitEvent(g_s2, g_evFork, 0);
    cudaMemsetAsync(out, 0, (size_t)out_size * sizeof(float), g_s2);

    gemm_softmax_kernel<<<ROWS / 64, 128>>>(X, W, noise);

    cudaEventRecord(g_evJoin, g_s2);
    cudaStreamWaitEvent(0, g_evJoin, 0);

    topk_kernel<<<BB * EE, 512>>>(out, out + HALF);
}

// round 8
// speedup vs baseline: 1.9533x; 1.9533x over previous
#include <cuda_runtime.h>
#include <stdint.h>

#define BB 4
#define SS 2048
#define DD 1024
#define EE 64
#define CC 64
#define ROWS (BB*SS)          // 8192
#define NOISE_SCALE (1.0f/64.0f)
#define HALF ((size_t)BB*SS*EE*CC)      // elements per output array
#define TOTAL_F4 ((2*HALF)/4)           // 16,777,216 float4 of output

#define NZERO 148                        // one zero block per SM (wave-1 placement)
#define NGEMM 256                        // 32-row gemm tiles
#define FAT_GRID (NZERO + NGEMM)         // 404 blocks, all resident in one wave
#define ZCHUNK 113664                    // float4 per zero block (148*113664 >= TOTAL_F4)

// Scratch: gates transposed [b][e][s]  (2 MB)
__device__ float g_gatesT[(size_t)BB*EE*SS];

// ---------------------------------------------------------------------------
// Fat kernel.
//  - Blocks 0..147: zero-fill (one per SM -> chip-wide store issue, dedicated
//    warps so store backpressure never blocks FFMA warps).
//  - Blocks 148..403: 32-row x 64-expert GEMM tile + noise + softmax.
//    2 gemm blocks/SM = 16 FFMA warps for latency hiding.
// ---------------------------------------------------------------------------
__global__ __launch_bounds__(256)
void fat_kernel(const float* __restrict__ X,
                const float* __restrict__ W,
                const float* __restrict__ noise,
                float4* __restrict__ out4)
{
    __shared__ float As[32][66];   // [row][k]
    __shared__ float Ws[64][64];   // [k][expert]; rows 0..31 reused for logits

    const int tid = threadIdx.x;

    if (blockIdx.x < NZERO) {
        // ---- zero path ----
        const float4 z = make_float4(0.f, 0.f, 0.f, 0.f);
        const size_t base = (size_t)blockIdx.x * ZCHUNK + tid;
#pragma unroll 4
        for (int q = 0; q < ZCHUNK / 256; q++) {
            size_t i = base + (size_t)q * 256;
            if (i < TOTAL_F4) out4[i] = z;
        }
        return;
    }

    // ---- gemm path ----
    const int g    = blockIdx.x - NZERO;       // 0..255
    const int tx   = tid & 15;                 // expert group (4 experts)
    const int ty   = tid >> 4;                 // row pair (2 rows)
    const int row0 = g * 32;

    float acc[2][4];
#pragma unroll
    for (int i = 0; i < 2; i++)
#pragma unroll
        for (int j = 0; j < 4; j++) acc[i][j] = 0.0f;

    for (int k0 = 0; k0 < DD; k0 += 64) {
        // A tile: 32 rows x 64 k  (512 float4, 2 per thread)
#pragma unroll
        for (int p = 0; p < 2; p++) {
            int r  = (tid >> 4) + p * 16;
            int kv = (tid & 15) * 4;
            float4 v = *(const float4*)&X[(size_t)(row0 + r) * DD + k0 + kv];
            As[r][kv + 0] = v.x;
            As[r][kv + 1] = v.y;
            As[r][kv + 2] = v.z;
            As[r][kv + 3] = v.w;
        }
        // W tile: 64 k x 64 experts (1024 float4, 4 per thread)
#pragma unroll
        for (int p = 0; p < 4; p++) {
            int kk = (tid >> 4) + p * 16;
            int ev = (tid & 15) * 4;
            *(float4*)&Ws[kk][ev] = *(const float4*)&W[(size_t)(k0 + kk) * EE + ev];
        }
        __syncthreads();

#pragma unroll
        for (int kk = 0; kk < 64; kk += 2) {
            float4 b0 = *(const float4*)&Ws[kk + 0][tx * 4];
            float4 b1 = *(const float4*)&Ws[kk + 1][tx * 4];
#pragma unroll
            for (int i = 0; i < 2; i++) {
                float2 a = *(const float2*)&As[ty * 2 + i][kk];
                acc[i][0] += a.x * b0.x; acc[i][1] += a.x * b0.y;
                acc[i][2] += a.x * b0.z; acc[i][3] += a.x * b0.w;
                acc[i][0] += a.y * b1.x; acc[i][1] += a.y * b1.y;
                acc[i][2] += a.y * b1.z; acc[i][3] += a.y * b1.w;
            }
        }
        __syncthreads();
    }

    // Epilogue: logits + noise into Ws rows 0..31
#pragma unroll
    for (int i = 0; i < 2; i++) {
        int r   = ty * 2 + i;
        int row = row0 + r;
#pragma unroll
        for (int j = 0; j < 4; j++) {
            int e = tx * 4 + j;
            Ws[r][e] = acc[i][j] + noise[(size_t)row * EE + e] * NOISE_SCALE;
        }
    }
    __syncthreads();

    // Softmax per row (threads 0..31), write transposed gates.
    if (tid < 32) {
        int r   = tid;
        int row = row0 + r;
        int b   = row / SS;
        int s   = row % SS;
        float m = -1e30f;
#pragma unroll
        for (int e = 0; e < EE; e++) m = fmaxf(m, Ws[r][e]);
        float sum = 0.0f;
#pragma unroll
        for (int e = 0; e < EE; e++) {
            float t = expf(Ws[r][e] - m);
            Ws[r][e] = t;
            sum += t;
        }
        float inv = 1.0f / sum;
#pragma unroll
        for (int e = 0; e < EE; e++) {
            g_gatesT[((size_t)b * EE + e) * SS + s] = Ws[r][e] * inv;
        }
    }
}

// ---------------------------------------------------------------------------
// Kernel 2: per-(b,e) exact top-64 via MSD radix select on u64 keys
// (gate_bits<<32)|~idx (distinct), parallel suffix-scan digit selection,
// adaptive bitonic sort of candidates, scatter. Grid: 256 blocks, 512 thr.
// ---------------------------------------------------------------------------
__global__ __launch_bounds__(512, 2)
void topk_kernel(float* __restrict__ mask_out,
                 float* __restrict__ comb_out)
{
    __shared__ unsigned long long keys[SS];
    __shared__ unsigned long long cand[512];
    __shared__ int hist[256];
    __shared__ unsigned long long s_prefix, s_thresh;
    __shared__ int s_need, s_done, s_cnt;

    const int tid = threadIdx.x;
    const int b = blockIdx.x >> 6;
    const int e = blockIdx.x & 63;

    const float* col = &g_gatesT[((size_t)b * EE + e) * SS];
    for (int i = tid; i < SS; i += 512) {
        unsigned int fb = __float_as_uint(col[i]);   // softmax gates > 0
        keys[i] = ((unsigned long long)fb << 32) | (unsigned int)(~i);
    }
    if (tid == 0) { s_done = 0; s_need = CC; s_prefix = 0ULL; }
    __syncthreads();

    for (int shift = 56; shift >= 0; shift -= 8) {
        if (s_done) break;
        const unsigned long long pf = s_prefix;
        const int need = s_need;
        if (tid < 256) hist[tid] = 0;
        __syncthreads();
        for (int i = tid; i < SS; i += 512) {
            unsigned long long k = keys[i];
            bool active = (shift == 56) || ((k >> (shift + 8)) == pf);
            if (active) atomicAdd(&hist[(int)((k >> shift) & 255)], 1);
        }
        __syncthreads();

#pragma unroll
        for (int off = 1; off < 256; off <<= 1) {
            int v = 0;
            if (tid < 256) {
                v = hist[tid];
                if (tid + off < 256) v += hist[tid + off];
            }
            __syncthreads();
            if (tid < 256) hist[tid] = v;
            __syncthreads();
        }

        if (tid < 256) {
            int c     = hist[tid];
            int above = (tid == 255) ? 0 : hist[tid + 1];
            if (c >= need && above < need) {
                int got = (CC - need) + c;
                unsigned long long np = (pf << 8) | (unsigned long long)tid;
                if (got <= 512 || shift == 0) {
                    s_thresh = np << shift;
                    s_done = 1;
                } else {
                    s_need = need - above;
                    s_prefix = np;
                }
            }
        }
        __syncthreads();
    }

    cand[tid & 511] = 0ULL;
    if (tid == 0) s_cnt = 0;
    __syncthreads();
    {
        const unsigned long long T = s_thresh;
        for (int i = tid; i < SS; i += 512) {
            unsigned long long k = keys[i];
            if (k >= T) { int p = atomicAdd(&s_cnt, 1); if (p < 512) cand[p] = k; }
        }
    }
    __syncthreads();

    int cnt = s_cnt;
    int nsort = 64;
    while (nsort < cnt && nsort < 512) nsort <<= 1;

    for (int k2 = 2; k2 <= nsort; k2 <<= 1) {
        for (int j = k2 >> 1; j > 0; j >>= 1) {
            if (tid < (nsort >> 1)) {
                int i   = ((tid & ~(j - 1)) << 1) | (tid & (j - 1));
                int ixj = i | j;
                bool desc = ((i & k2) == 0);
                unsigned long long a = cand[i];
                unsigned long long c = cand[ixj];
                if ((a < c) == desc) { cand[i] = c; cand[ixj] = a; }
            }
            __syncthreads();
        }
    }

    if (tid < CC) {
        unsigned long long k = cand[tid];
        int   s = (int)(~(unsigned int)k);
        float v = __uint_as_float((unsigned int)(k >> 32));
        size_t idx = ((((size_t)b * SS + s) * EE + e) << 6) + tid;
        mask_out[idx] = 1.0f;
        comb_out[idx] = v;
    }
}

// ---------------------------------------------------------------------------
extern "C" void kernel_launch(void* const* d_in, const int* in_sizes, int n_in,
                              void* d_out, int out_size)
{
    const float* X     = (const float*)d_in[0];   // [B,S,D]
    const float* W     = (const float*)d_in[1];   // [D,E]
    const float* noise = (const float*)d_in[2];   // [B,S,E]
    float* out = (float*)d_out;

    fat_kernel<<<FAT_GRID, 256>>>(X, W, noise, (float4*)out);
    topk_kernel<<<BB * EE, 512>>>(out, out + HALF);
}

// round 9
// speedup vs baseline: 1.9595x; 1.0032x over previous
#include <cuda_runtime.h>
#include <stdint.h>

#define BB 4
#define SS 2048
#define DD 1024
#define EE 64
#define CC 64
#define ROWS (BB*SS)          // 8192
#define NOISE_SCALE (1.0f/64.0f)
#define HALF ((size_t)BB*SS*EE*CC)      // elements per output array

// Scratch: gates transposed [b][e][s]  (2 MB)
__device__ float g_gatesT[(size_t)BB*EE*SS];

// ---------------------------------------------------------------------------
// Kernel 1: scalar-FFMA GEMM + noise + softmax -> gatesT.
// 256 blocks x 256 threads, 32-row x 64-expert tile, thread tile 2x4.
// ~2 blocks/SM (16 warps) on all 148 SMs; inner mix 20 issues / 32 fma-pipe
// cycles per 2-kk -> fma-pipe-bound.
// ---------------------------------------------------------------------------
__global__ __launch_bounds__(256, 2)
void gemm_softmax_kernel(const float* __restrict__ X,
                         const float* __restrict__ W,
                         const float* __restrict__ noise)
{
    __shared__ float As[32][66];   // [row][k]
    __shared__ float Ws[64][64];   // [k][expert]; rows 0..31 reused for logits

    const int tid  = threadIdx.x;
    const int tx   = tid & 15;                 // expert group (4 experts)
    const int ty   = tid >> 4;                 // row pair (2 rows)
    const int row0 = blockIdx.x * 32;

    float acc[2][4];
#pragma unroll
    for (int i = 0; i < 2; i++)
#pragma unroll
        for (int j = 0; j < 4; j++) acc[i][j] = 0.0f;

    for (int k0 = 0; k0 < DD; k0 += 64) {
        // A tile: 32 rows x 64 k  (512 float4, 2 per thread)
#pragma unroll
        for (int p = 0; p < 2; p++) {
            int r  = (tid >> 4) + p * 16;
            int kv = (tid & 15) * 4;
            float4 v = *(const float4*)&X[(size_t)(row0 + r) * DD + k0 + kv];
            As[r][kv + 0] = v.x;
            As[r][kv + 1] = v.y;
            As[r][kv + 2] = v.z;
            As[r][kv + 3] = v.w;
        }
        // W tile: 64 k x 64 experts (1024 float4, 4 per thread)
#pragma unroll
        for (int p = 0; p < 4; p++) {
            int kk = (tid >> 4) + p * 16;
            int ev = (tid & 15) * 4;
            *(float4*)&Ws[kk][ev] = *(const float4*)&W[(size_t)(k0 + kk) * EE + ev];
        }
        __syncthreads();

#pragma unroll
        for (int kk = 0; kk < 64; kk += 2) {
            float4 b0 = *(const float4*)&Ws[kk + 0][tx * 4];
            float4 b1 = *(const float4*)&Ws[kk + 1][tx * 4];
#pragma unroll
            for (int i = 0; i < 2; i++) {
                float2 a = *(const float2*)&As[ty * 2 + i][kk];
                acc[i][0] += a.x * b0.x; acc[i][1] += a.x * b0.y;
                acc[i][2] += a.x * b0.z; acc[i][3] += a.x * b0.w;
                acc[i][0] += a.y * b1.x; acc[i][1] += a.y * b1.y;
                acc[i][2] += a.y * b1.z; acc[i][3] += a.y * b1.w;
            }
        }
        __syncthreads();
    }

    // Epilogue: logits + noise into Ws rows 0..31
#pragma unroll
    for (int i = 0; i < 2; i++) {
        int r   = ty * 2 + i;
        int row = row0 + r;
#pragma unroll
        for (int j = 0; j < 4; j++) {
            int e = tx * 4 + j;
            Ws[r][e] = acc[i][j] + noise[(size_t)row * EE + e] * NOISE_SCALE;
        }
    }
    __syncthreads();

    // Softmax per row (threads 0..31), write transposed gates.
    if (tid < 32) {
        int r   = tid;
        int row = row0 + r;
        int b   = row / SS;
        int s   = row % SS;
        float m = -1e30f;
#pragma unroll
        for (int e = 0; e < EE; e++) m = fmaxf(m, Ws[r][e]);
        float sum = 0.0f;
#pragma unroll
        for (int e = 0; e < EE; e++) {
            float t = expf(Ws[r][e] - m);
            Ws[r][e] = t;
            sum += t;
        }
        float inv = 1.0f / sum;
#pragma unroll
        for (int e = 0; e < EE; e++) {
            g_gatesT[((size_t)b * EE + e) * SS + s] = Ws[r][e] * inv;
        }
    }
}

// ---------------------------------------------------------------------------
// Kernel 2: per-(b,e) exact top-64 via MSD radix select on u64 keys
// (gate_bits<<32)|~idx (distinct), parallel suffix-scan digit selection,
// adaptive bitonic sort of candidates, scatter. Grid: 256 blocks, 512 thr.
// ---------------------------------------------------------------------------
__global__ __launch_bounds__(512, 2)
void topk_kernel(float* __restrict__ mask_out,
                 float* __restrict__ comb_out)
{
    __shared__ unsigned long long keys[SS];
    __shared__ unsigned long long cand[512];
    __shared__ int hist[256];
    __shared__ unsigned long long s_prefix, s_thresh;
    __shared__ int s_need, s_done, s_cnt;

    const int tid = threadIdx.x;
    const int b = blockIdx.x >> 6;
    const int e = blockIdx.x & 63;

    const float* col = &g_gatesT[((size_t)b * EE + e) * SS];
    for (int i = tid; i < SS; i += 512) {
        unsigned int fb = __float_as_uint(col[i]);   // softmax gates > 0
        keys[i] = ((unsigned long long)fb << 32) | (unsigned int)(~i);
    }
    if (tid == 0) { s_done = 0; s_need = CC; s_prefix = 0ULL; }
    __syncthreads();

    for (int shift = 56; shift >= 0; shift -= 8) {
        if (s_done) break;
        const unsigned long long pf = s_prefix;
        const int need = s_need;
        if (tid < 256) hist[tid] = 0;
        __syncthreads();
        for (int i = tid; i < SS; i += 512) {
            unsigned long long k = keys[i];
            bool active = (shift == 56) || ((k >> (shift + 8)) == pf);
            if (active) atomicAdd(&hist[(int)((k >> shift) & 255)], 1);
        }
        __syncthreads();

#pragma unroll
        for (int off = 1; off < 256; off <<= 1) {
            int v = 0;
            if (tid < 256) {
                v = hist[tid];
                if (tid + off < 256) v += hist[tid + off];
            }
            __syncthreads();
            if (tid < 256) hist[tid] = v;
            __syncthreads();
        }

        if (tid < 256) {
            int c     = hist[tid];
            int above = (tid == 255) ? 0 : hist[tid + 1];
            if (c >= need && above < need) {
                int got = (CC - need) + c;
                unsigned long long np = (pf << 8) | (unsigned long long)tid;
                if (got <= 512 || shift == 0) {
                    s_thresh = np << shift;
                    s_done = 1;
                } else {
                    s_need = need - above;
                    s_prefix = np;
                }
            }
        }
        __syncthreads();
    }

    cand[tid & 511] = 0ULL;
    if (tid == 0) s_cnt = 0;
    __syncthreads();
    {
        const unsigned long long T = s_thresh;
        for (int i = tid; i < SS; i += 512) {
            unsigned long long k = keys[i];
            if (k >= T) { int p = atomicAdd(&s_cnt, 1); if (p < 512) cand[p] = k; }
        }
    }
    __syncthreads();

    int cnt = s_cnt;
    int nsort = 64;
    while (nsort < cnt && nsort < 512) nsort <<= 1;

    for (int k2 = 2; k2 <= nsort; k2 <<= 1) {
        for (int j = k2 >> 1; j > 0; j >>= 1) {
            if (tid < (nsort >> 1)) {
                int i   = ((tid & ~(j - 1)) << 1) | (tid & (j - 1));
                int ixj = i | j;
                bool desc = ((i & k2) == 0);
                unsigned long long a = cand[i];
                unsigned long long c = cand[ixj];
                if ((a < c) == desc) { cand[i] = c; cand[ixj] = a; }
            }
            __syncthreads();
        }
    }

    if (tid < CC) {
        unsigned long long k = cand[tid];
        int   s = (int)(~(unsigned int)k);
        float v = __uint_as_float((unsigned int)(k >> 32));
        size_t idx = ((((size_t)b * SS + s) * EE + e) << 6) + tid;
        mask_out[idx] = 1.0f;
        comb_out[idx] = v;
    }
}

// ---------------------------------------------------------------------------
// Launch: plain serial pipeline — overlap is structurally unprofitable here
// (5 schemes all collapsed to serial-sum; stores and LDS share the L1TEX
// queue). memset (driver, fastest 268MB zero) -> gemm -> topk.
// ---------------------------------------------------------------------------
extern "C" void kernel_launch(void* const* d_in, const int* in_sizes, int n_in,
                              void* d_out, int out_size)
{
    const float* X     = (const float*)d_in[0];   // [B,S,D]
    const float* W     = (const float*)d_in[1];   // [D,E]
    const float* noise = (const float*)d_in[2];   // [B,S,E]
    float* out = (float*)d_out;

    cudaMemsetAsync(out, 0, (size_t)out_size * sizeof(float), 0);
    gemm_softmax_kernel<<<ROWS / 32, 256>>>(X, W, noise);
    topk_kernel<<<BB * EE, 512>>>(out, out + HALF);
}

// round 11
// speedup vs baseline: 2.4761x; 1.2636x over previous
#include <cuda_runtime.h>
#include <stdint.h>

#define BB 4
#define SS 2048
#define DD 1024
#define EE 64
#define CC 64
#define ROWS (BB*SS)          // 8192
#define NOISE_SCALE (1.0f/64.0f)
#define HALF ((size_t)BB*SS*EE*CC)      // elements per output array

// Dynamic smem layout (floats):
//   As: 2 buffers x 64 rows x 68 stride  (stride 68 -> 16B-aligned rows for cp.async)
//   Ws: 2 buffers x 64 k    x 64 experts
#define AS_STRIDE 68
#define AS_FLOATS (2*64*AS_STRIDE)      // 8704
#define WS_FLOATS (2*64*64)             // 8192
#define SMEM_FLOATS (AS_FLOATS + WS_FLOATS)
#define SMEM_BYTES (SMEM_FLOATS*4)      // 67584

// Scratch: gates transposed [b][e][s]  (2 MB)
__device__ float g_gatesT[(size_t)BB*EE*SS];

__device__ __forceinline__ void cp_async16(uint32_t dst_smem, const void* src) {
    asm volatile("cp.async.cg.shared.global [%0], [%1], 16;" :: "r"(dst_smem), "l"(src));
}

// ---------------------------------------------------------------------------
// Kernel 1: GEMM + noise + softmax -> gatesT.
// Identical math/order to the proven R1 kernel (64x64 tile, 4x4 thread tile,
// k ascending, single accumulator per output -> bit-identical gates), but the
// 16 outer-iteration tile loads are cp.async double-buffered so DRAM latency
// hides under the FFMA stream. One __syncthreads per outer iteration.
// ---------------------------------------------------------------------------
__global__ __launch_bounds__(256)
void gemm_softmax_kernel(const float* __restrict__ X,
                         const float* __restrict__ W,
                         const float* __restrict__ noise)
{
    extern __shared__ float smem[];
    float* sA = smem;               // [2][64][AS_STRIDE]
    float* sW = smem + AS_FLOATS;   // [2][64][64]

    const int tid  = threadIdx.x;
    const int tx   = tid & 15;      // expert group (4 experts)
    const int ty   = tid >> 4;      // row group (4 rows)
    const int row0 = blockIdx.x * 64;

    uint32_t smem_u32 = (uint32_t)__cvta_generic_to_shared(smem);
    const uint32_t a_base = smem_u32;
    const uint32_t w_base = smem_u32 + AS_FLOATS * 4;

    // Per-thread load coordinates (fixed across iterations)
    const int lr = tid >> 4;        // 0..15 (row / k stride base)
    const int lc = (tid & 15) * 4;  // 0..60 (float4 column)

    // ---- preload tile 0 into buffer 0 ----
    {
        const int k0 = 0;
#pragma unroll
        for (int p = 0; p < 4; p++) {
            int r = lr + p * 16;
            cp_async16(a_base + (uint32_t)((r * AS_STRIDE + lc) * 4),
                       &X[(size_t)(row0 + r) * DD + k0 + lc]);
        }
#pragma unroll
        for (int p = 0; p < 4; p++) {
            int kk = lr + p * 16;
            cp_async16(w_base + (uint32_t)((kk * 64 + lc) * 4),
                       &W[(size_t)(k0 + kk) * EE + lc]);
        }
        asm volatile("cp.async.commit_group;");
    }

    float acc[4][4];
#pragma unroll
    for (int i = 0; i < 4; i++)
#pragma unroll
        for (int j = 0; j < 4; j++) acc[i][j] = 0.0f;

    for (int it = 0; it < 16; it++) {
        const int buf = it & 1;

        asm volatile("cp.async.wait_group 0;");
        __syncthreads();

        // Prefetch next tile into the other buffer (overlaps compute below)
        if (it < 15) {
            const int k1 = (it + 1) * 64;
            const int nb = buf ^ 1;
            const uint32_t a_off = a_base + (uint32_t)(nb * 64 * AS_STRIDE * 4);
            const uint32_t w_off = w_base + (uint32_t)(nb * 64 * 64 * 4);
#pragma unroll
            for (int p = 0; p < 4; p++) {
                int r = lr + p * 16;
                cp_async16(a_off + (uint32_t)((r * AS_STRIDE + lc) * 4),
                           &X[(size_t)(row0 + r) * DD + k1 + lc]);
            }
#pragma unroll
            for (int p = 0; p < 4; p++) {
                int kk = lr + p * 16;
                cp_async16(w_off + (uint32_t)((kk * 64 + lc) * 4),
                           &W[(size_t)(k1 + kk) * EE + lc]);
            }
            asm volatile("cp.async.commit_group;");
        }

        // Compute on current buffer — exact R1 inner loop (bit-identical order)
        const float* A = sA + buf * 64 * AS_STRIDE;
        const float* Bm = sW + buf * 64 * 64;
#pragma unroll
        for (int kk = 0; kk < 64; kk += 2) {
            float4 b0 = *(const float4*)&Bm[(kk + 0) * 64 + tx * 4];
            float4 b1 = *(const float4*)&Bm[(kk + 1) * 64 + tx * 4];
#pragma unroll
            for (int i = 0; i < 4; i++) {
                float2 a = *(const float2*)&A[(ty * 4 + i) * AS_STRIDE + kk];
                acc[i][0] += a.x * b0.x; acc[i][1] += a.x * b0.y;
                acc[i][2] += a.x * b0.z; acc[i][3] += a.x * b0.w;
                acc[i][0] += a.y * b1.x; acc[i][1] += a.y * b1.y;
                acc[i][2] += a.y * b1.z; acc[i][3] += a.y * b1.w;
            }
        }
        __syncthreads();   // all warps done with this buffer before it is refilled
    }

    // Epilogue: logits + noise into sW buffer 0 (reused as [row][expert])
    float* L = sW;
#pragma unroll
    for (int i = 0; i < 4; i++) {
        int r   = ty * 4 + i;
        int row = row0 + r;
#pragma unroll
        for (int j = 0; j < 4; j++) {
            int e = tx * 4 + j;
            L[r * 64 + e] = acc[i][j] + noise[(size_t)row * EE + e] * NOISE_SCALE;
        }
    }
    __syncthreads();

    // Softmax per row (threads 0..63), write transposed gates.
    if (tid < 64) {
        int r   = tid;
        int row = row0 + r;
        int b   = row / SS;
        int s   = row % SS;
        float m = -1e30f;
#pragma unroll
        for (int e = 0; e < EE; e++) m = fmaxf(m, L[r * 64 + e]);
        float sum = 0.0f;
#pragma unroll
        for (int e = 0; e < EE; e++) {
            float t = expf(L[r * 64 + e] - m);
            L[r * 64 + e] = t;
            sum += t;
        }
        float inv = 1.0f / sum;
#pragma unroll
        for (int e = 0; e < EE; e++) {
            g_gatesT[((size_t)b * EE + e) * SS + s] = L[r * 64 + e] * inv;
        }
    }
}

// ---------------------------------------------------------------------------
// Kernel 2: per-(b,e) exact top-64 via MSD radix select on u64 keys
// (gate_bits<<32)|~idx (distinct), parallel suffix-scan digit selection,
// adaptive bitonic sort of candidates, scatter. Grid: 256 blocks, 512 thr.
// ---------------------------------------------------------------------------
__global__ __launch_bounds__(512, 2)
void topk_kernel(float* __restrict__ mask_out,
                 float* __restrict__ comb_out)
{
    __shared__ unsigned long long keys[SS];
    __shared__ unsigned long long cand[512];
    __shared__ int hist[256];
    __shared__ unsigned long long s_prefix, s_thresh;
    __shared__ int s_need, s_done, s_cnt;

    const int tid = threadIdx.x;
    const int b = blockIdx.x >> 6;
    const int e = blockIdx.x & 63;

    const float* col = &g_gatesT[((size_t)b * EE + e) * SS];
    for (int i = tid; i < SS; i += 512) {
        unsigned int fb = __float_as_uint(col[i]);   // softmax gates > 0
        keys[i] = ((unsigned long long)fb << 32) | (unsigned int)(~i);
    }
    if (tid == 0) { s_done = 0; s_need = CC; s_prefix = 0ULL; }
    __syncthreads();

    for (int shift = 56; shift >= 0; shift -= 8) {
        if (s_done) break;
        const unsigned long long pf = s_prefix;
        const int need = s_need;
        if (tid < 256) hist[tid] = 0;
        __syncthreads();
        for (int i = tid; i < SS; i += 512) {
            unsigned long long k = keys[i];
            bool active = (shift == 56) || ((k >> (shift + 8)) == pf);
            if (active) atomicAdd(&hist[(int)((k >> shift) & 255)], 1);
        }
        __syncthreads();

#pragma unroll
        for (int off = 1; off < 256; off <<= 1) {
            int v = 0;
            if (tid < 256) {
                v = hist[tid];
                if (tid + off < 256) v += hist[tid + off];
            }
            __syncthreads();
            if (tid < 256) hist[tid] = v;
            __syncthreads();
        }

        if (tid < 256) {
            int c     = hist[tid];
            int above = (tid == 255) ? 0 : hist[tid + 1];
            if (c >= need && above < need) {
                int got = (CC - need) + c;
                unsigned long long np = (pf << 8) | (unsigned long long)tid;
                if (got <= 512 || shift == 0) {
                    s_thresh = np << shift;
                    s_done = 1;
                } else {
                    s_need = need - above;
                    s_prefix = np;
                }
            }
        }
        __syncthreads();
    }

    cand[tid & 511] = 0ULL;
    if (tid == 0) s_cnt = 0;
    __syncthreads();
    {
        const unsigned long long T = s_thresh;
        for (int i = tid; i < SS; i += 512) {
            unsigned long long k = keys[i];
            if (k >= T) { int p = atomicAdd(&s_cnt, 1); if (p < 512) cand[p] = k; }
        }
    }
    __syncthreads();

    int cnt = s_cnt;
    int nsort = 64;
    while (nsort < cnt && nsort < 512) nsort <<= 1;

    for (int k2 = 2; k2 <= nsort; k2 <<= 1) {
        for (int j = k2 >> 1; j > 0; j >>= 1) {
            if (tid < (nsort >> 1)) {
                int i   = ((tid & ~(j - 1)) << 1) | (tid & (j - 1));
                int ixj = i | j;
                bool desc = ((i & k2) == 0);
                unsigned long long a = cand[i];
                unsigned long long c = cand[ixj];
                if ((a < c) == desc) { cand[i] = c; cand[ixj] = a; }
            }
            __syncthreads();
        }
    }

    if (tid < CC) {
        unsigned long long k = cand[tid];
        int   s = (int)(~(unsigned int)k);
        float v = __uint_as_float((unsigned int)(k >> 32));
        size_t idx = ((((size_t)b * SS + s) * EE + e) << 6) + tid;
        mask_out[idx] = 1.0f;
        comb_out[idx] = v;
    }
}

// ---------------------------------------------------------------------------
// Serial pipeline: memset -> double-buffered gemm -> topk.
// ---------------------------------------------------------------------------
extern "C" void kernel_launch(void* const* d_in, const int* in_sizes, int n_in,
                              void* d_out, int out_size)
{
    const float* X     = (const float*)d_in[0];   // [B,S,D]
    const float* W     = (const float*)d_in[1];   // [D,E]
    const float* noise = (const float*)d_in[2];   // [B,S,E]
    float* out = (float*)d_out;

    cudaFuncSetAttribute(gemm_softmax_kernel,
                         cudaFuncAttributeMaxDynamicSharedMemorySize, SMEM_BYTES);

    cudaMemsetAsync(out, 0, (size_t)out_size * sizeof(float), 0);
    gemm_softmax_kernel<<<ROWS / 64, 256, SMEM_BYTES>>>(X, W, noise);
    topk_kernel<<<BB * EE, 512>>>(out, out + HALF);
}